// round 9
// baseline (speedup 1.0000x reference)
#include <cuda_runtime.h>
#include <stdint.h>

#define BATCH 4
#define SEQ   2048
#define DMOD  1024

#define NQ ((long)BATCH*SEQ*DMOD)   // 8,388,608
#define NW ((long)DMOD*DMOD)        // 1,048,576
#define NS ((long)BATCH*SEQ*SEQ)    // 16,777,216

// ----------------------------------------------------------------------------
// Scratch (device globals; allocation is forbidden)
// ----------------------------------------------------------------------------
// int8 digit planes
__device__ __align__(256) int8_t g_xq0[NQ], g_xq1[NQ];
__device__ __align__(256) int8_t g_xk0[NQ], g_xk1[NQ];
__device__ __align__(256) int8_t g_xv0[NQ], g_xv1[NQ];
__device__ __align__(256) int8_t g_wq0[NW], g_wq1[NW];
__device__ __align__(256) int8_t g_wk0[NW], g_wk1[NW];
__device__ __align__(256) int8_t g_wv0[NW], g_wv1[NW];
__device__ __align__(256) int8_t g_wo0[NW], g_wo1[NW];
__device__ __align__(256) int8_t g_qp0[NQ], g_qp1[NQ];
__device__ __align__(256) int8_t g_kp0[NQ], g_kp1[NQ];
__device__ __align__(256) int8_t g_vT0[NQ], g_vT1[NQ];   // [B][D][S]
__device__ __align__(256) int8_t g_at0[NS], g_at1[NS];
__device__ __align__(256) int8_t g_av0[NQ], g_av1[NQ];
// fp32 intermediates
__device__ __align__(256) float g_qpf[NQ], g_kpf[NQ], g_vTf[NQ], g_avf[NQ];
__device__ __align__(256) float g_sc[NS];
// per-row scales
__device__ __align__(256) float g_sxq[8192], g_sxk[8192], g_sxv[8192];
__device__ __align__(256) float g_swq[1024], g_swk[1024], g_swv[1024], g_swo[1024];
__device__ __align__(256) float g_sqp[8192], g_skp[8192], g_svT[4096];
__device__ __align__(256) float g_sat[8192], g_sav[8192];

// ----------------------------------------------------------------------------
// helpers
// ----------------------------------------------------------------------------
__device__ __forceinline__ uint32_t smem_u32(const void* p) {
    uint32_t a;
    asm("{ .reg .u64 t; cvta.to.shared.u64 t, %1; cvt.u32.u64 %0, t; }" : "=r"(a) : "l"(p));
    return a;
}
__device__ __forceinline__ void cp16(uint32_t s, const void* g) {
    asm volatile("cp.async.cg.shared.global [%0], [%1], 16;" :: "r"(s), "l"(g));
}
#define CP_COMMIT() asm volatile("cp.async.commit_group;" ::: "memory")
#define CP_WAIT(n)  asm volatile("cp.async.wait_group %0;" :: "n"(n) : "memory")

__device__ __forceinline__ void ldsm4(uint32_t& r0, uint32_t& r1, uint32_t& r2,
                                      uint32_t& r3, uint32_t addr) {
    asm volatile("ldmatrix.sync.aligned.m8n8.x4.shared.b16 {%0,%1,%2,%3}, [%4];"
                 : "=r"(r0), "=r"(r1), "=r"(r2), "=r"(r3) : "r"(addr));
}
// int8 MMA, 2048 MAC/instr, exact s32 accumulate
__device__ __forceinline__ void imma16832(int* d, const uint32_t* a, const uint32_t* b) {
    asm volatile(
        "mma.sync.aligned.m16n8k32.row.col.s32.s8.s8.s32 "
        "{%0,%1,%2,%3}, {%4,%5,%6,%7}, {%8,%9}, {%0,%1,%2,%3};"
        : "+r"(d[0]), "+r"(d[1]), "+r"(d[2]), "+r"(d[3])
        : "r"(a[0]), "r"(a[1]), "r"(a[2]), "r"(a[3]), "r"(b[0]), "r"(b[1]));
}

// ----------------------------------------------------------------------------
// per-row 2-digit int8 quantization: x ~= s*(a0 + a1/128), s = rowmax/127
// ----------------------------------------------------------------------------
__global__ void quant_rows(const float* __restrict__ x, int8_t* __restrict__ d0,
                           int8_t* __restrict__ d1, float* __restrict__ sc, int L) {
    const float* row = x + (long)blockIdx.x * L;
    __shared__ float red[256];
    const int t = threadIdx.x;
    const int per = L >> 8;              // 4 or 8
    float v[8];
    float m = 0.f;
    for (int i = 0; i < per; ++i) {
        v[i] = row[t + (i << 8)];
        m = fmaxf(m, fabsf(v[i]));
    }
    red[t] = m; __syncthreads();
    for (int s = 128; s > 0; s >>= 1) {
        if (t < s) red[t] = fmaxf(red[t], red[t + s]);
        __syncthreads();
    }
    const float mx = red[0];
    const float inv = (mx > 0.f) ? (127.f / mx) : 0.f;
    if (t == 0) sc[blockIdx.x] = mx / 127.f;
    const long base = (long)blockIdx.x * L;
    for (int i = 0; i < per; ++i) {
        float y = v[i] * inv;
        int a0 = __float2int_rn(y);
        int a1 = __float2int_rn((y - (float)a0) * 128.f);
        d0[base + t + (i << 8)] = (int8_t)a0;
        d1[base + t + (i << 8)] = (int8_t)a1;
    }
}

// ----------------------------------------------------------------------------
// Row softmax fp32 -> int8 2-digit   (n == 2048, 256 threads)
// probs p = e*inv, rowmax(p) = inv  ->  p/scale = 127*e
// ----------------------------------------------------------------------------
__global__ void softmax_quant(const float* __restrict__ S, int8_t* __restrict__ d0,
                              int8_t* __restrict__ d1, float* __restrict__ sc, int n) {
    const float* row = S + (long)blockIdx.x * n;
    __shared__ float red[256];
    const int t = threadIdx.x;
    float e[8];
    float m = -1e30f;
#pragma unroll
    for (int i = 0; i < 8; i++) { e[i] = row[t + i * 256]; m = fmaxf(m, e[i]); }
    red[t] = m; __syncthreads();
    for (int s = 128; s > 0; s >>= 1) {
        if (t < s) red[t] = fmaxf(red[t], red[t + s]);
        __syncthreads();
    }
    m = red[0]; __syncthreads();
    float sum = 0.f;
#pragma unroll
    for (int i = 0; i < 8; i++) { e[i] = __expf(e[i] - m); sum += e[i]; }
    red[t] = sum; __syncthreads();
    for (int s = 128; s > 0; s >>= 1) {
        if (t < s) red[t] += red[t + s];
        __syncthreads();
    }
    const float inv = 1.0f / red[0];
    if (t == 0) sc[blockIdx.x] = inv / 127.f;
    const long base = (long)blockIdx.x * n;
#pragma unroll
    for (int i = 0; i < 8; i++) {
        float y = e[i] * 127.f;          // p / scale
        int a0 = __float2int_rn(y);
        int a1 = __float2int_rn((y - (float)a0) * 128.f);
        d0[base + t + i * 256] = (int8_t)a0;
        d1[base + t + i * 256] = (int8_t)a1;
    }
}

// ----------------------------------------------------------------------------
// int8 3-product GEMM (NT): C[m,n] = alpha*sA[m]*sB[n]*(acc1 + acc2/128) (+bias)
//   acc1 = A0*B0, acc2 = A0*B1 + A1*B0  (A1*B1 dropped, ~6e-5 rel)
//   CTA tile 128x128, KC=64 int8, 2-stage cp.async, 8 warps (64x32 each).
// ----------------------------------------------------------------------------
#define KC 64
#define ROWB 80              // 64B data + 16B pad
#define TILEB (128 * ROWB)   // 10240
#define SM_A0 0
#define SM_A1 TILEB
#define SM_B0 (2 * TILEB)
#define SM_B1 (3 * TILEB)
#define STAGEB (4 * TILEB)   // 40960
#define SMEM_BYTES (2 * STAGEB)   // 81920

__global__ void __launch_bounds__(256) gemm_i8(
    const int8_t* __restrict__ A0, const int8_t* __restrict__ A1,
    const float* __restrict__ sA,
    const int8_t* __restrict__ B0, const int8_t* __restrict__ B1,
    const float* __restrict__ sB,
    const float* __restrict__ bias, float* __restrict__ C,
    int N, int K, int ldc, float alpha,
    long strA, long strB, long strC, long sAstr, long sBstr, int transC)
{
    extern __shared__ char smem[];
    const uint32_t sb = smem_u32(smem);
    const int tid = threadIdx.x;
    const int wid = tid >> 5;
    const int lid = tid & 31;
    const int wm = (wid & 1) * 64;
    const int wn = (wid >> 1) * 32;
    const long bz = blockIdx.z;
    const int m0 = blockIdx.y * 128;
    const int n0 = blockIdx.x * 128;

    const int8_t* pA0 = A0 + bz * strA;
    const int8_t* pA1 = A1 + bz * strA;
    const int8_t* pB0 = B0 + bz * strB;
    const int8_t* pB1 = B1 + bz * strB;
    const float* psA = sA + bz * sAstr;
    const float* psB = sB + bz * sBstr;
    float* pC = C + bz * strC;

    int acc1[4][4][4], acc2[4][4][4];
#pragma unroll
    for (int i = 0; i < 4; ++i)
#pragma unroll
        for (int j = 0; j < 4; ++j)
#pragma unroll
            for (int c = 0; c < 4; ++c) { acc1[i][j][c] = 0; acc2[i][j][c] = 0; }

    const int nch = K / KC;
    const int lrow  = tid >> 1;          // 0..127
    const int lhalf = (tid & 1) * 32;    // 0 or 32 bytes

    // ---- stage loader: 8 x cp16 per thread (1 row x 4 tiles x 32B) ----
    auto issue = [&](int ch, int buf) {
        const int k0 = ch * KC;
        const uint32_t s0 = sb + buf * STAGEB;
        const uint32_t so = (uint32_t)(lrow * ROWB + lhalf);
        const long gA = (long)(m0 + lrow) * K + k0 + lhalf;
        const long gB = (long)(n0 + lrow) * K + k0 + lhalf;
        cp16(s0 + SM_A0 + so,      pA0 + gA);
        cp16(s0 + SM_A0 + so + 16, pA0 + gA + 16);
        cp16(s0 + SM_A1 + so,      pA1 + gA);
        cp16(s0 + SM_A1 + so + 16, pA1 + gA + 16);
        cp16(s0 + SM_B0 + so,      pB0 + gB);
        cp16(s0 + SM_B0 + so + 16, pB0 + gB + 16);
        cp16(s0 + SM_B1 + so,      pB1 + gB);
        cp16(s0 + SM_B1 + so + 16, pB1 + gB + 16);
    };

    issue(0, 0);
    CP_COMMIT();

    // ldmatrix lane addressing (identical structure to fp16 16816; 16B = 16 k-bytes)
    const int a_row = lid & 15;
    const int a_col = (lid >> 4) * 16;
    const int b_nin = ((lid >> 4) & 1) * 8 + (lid & 7);
    const int b_col = ((lid >> 3) & 1) * 16;

    for (int ch = 0; ch < nch; ++ch) {
        if (ch + 1 < nch) { issue(ch + 1, (ch + 1) & 1); CP_COMMIT(); CP_WAIT(1); }
        else              { CP_WAIT(0); }
        __syncthreads();

        const uint32_t s0 = sb + (ch & 1) * STAGEB;

#pragma unroll
        for (int ks = 0; ks < 2; ++ks) {           // 32 k-bytes per step
            const int kb = ks * 32 + a_col;
            uint32_t a0f[4][4], a1f[4][4];
#pragma unroll
            for (int mt = 0; mt < 4; ++mt) {
                const uint32_t ro = (uint32_t)((wm + mt * 16 + a_row) * ROWB);
                ldsm4(a0f[mt][0], a0f[mt][1], a0f[mt][2], a0f[mt][3], s0 + SM_A0 + ro + kb);
                ldsm4(a1f[mt][0], a1f[mt][1], a1f[mt][2], a1f[mt][3], s0 + SM_A1 + ro + kb);
            }
            uint32_t b0f[2][4], b1f[2][4];
#pragma unroll
            for (int np = 0; np < 2; ++np) {
                const uint32_t ro = (uint32_t)((wn + np * 16 + b_nin) * ROWB + ks * 32 + b_col);
                ldsm4(b0f[np][0], b0f[np][1], b0f[np][2], b0f[np][3], s0 + SM_B0 + ro);
                ldsm4(b1f[np][0], b1f[np][1], b1f[np][2], b1f[np][3], s0 + SM_B1 + ro);
            }
            // interleaved per-(mt,nt) product triple (R3/R5-style ordering)
#pragma unroll
            for (int mt = 0; mt < 4; ++mt) {
#pragma unroll
                for (int nt = 0; nt < 4; ++nt) {
                    const int np = nt >> 1, sel = (nt & 1) * 2;
                    imma16832(acc1[mt][nt], a0f[mt], &b0f[np][sel]);
                    imma16832(acc2[mt][nt], a0f[mt], &b1f[np][sel]);
                    imma16832(acc2[mt][nt], a1f[mt], &b0f[np][sel]);
                }
            }
        }
        __syncthreads();
    }

    // ---- epilogue: dequantize ----
    const int gr = lid >> 2;
    const int tg = lid & 3;
#pragma unroll
    for (int mt = 0; mt < 4; ++mt) {
#pragma unroll
        for (int nt = 0; nt < 4; ++nt) {
#pragma unroll
            for (int h = 0; h < 2; ++h) {
                const int m = m0 + wm + mt * 16 + gr + h * 8;
                const float sam = __ldg(psA + m) * alpha;
#pragma unroll
                for (int c = 0; c < 2; ++c) {
                    const int n = n0 + wn + nt * 8 + tg * 2 + c;
                    float v = ((float)acc1[mt][nt][h * 2 + c] +
                               (float)acc2[mt][nt][h * 2 + c] * (1.0f / 128.0f))
                              * sam * __ldg(psB + n);
                    if (bias) v += __ldg(bias + n);
                    if (transC) {
                        // v-proj: m = bz*2048 + s (batch-major); write [b][n][s]
                        long o = (long)(m >> 11) * ((long)DMOD * SEQ) + (long)n * SEQ + (m & 2047);
                        pC[o] = v;
                    } else {
                        pC[(long)m * ldc + n] = v;
                    }
                }
            }
        }
    }
}

// ----------------------------------------------------------------------------
// launch
// ----------------------------------------------------------------------------
extern "C" void kernel_launch(void* const* d_in, const int* in_sizes, int n_in,
                              void* d_out, int out_size) {
    const float* q  = (const float*)d_in[0];
    const float* k  = (const float*)d_in[1];
    const float* v  = (const float*)d_in[2];
    const float* Wq = (const float*)d_in[3];
    const float* bq = (const float*)d_in[4];
    const float* Wk = (const float*)d_in[5];
    const float* bk = (const float*)d_in[6];
    const float* Wv = (const float*)d_in[7];
    const float* bv = (const float*)d_in[8];
    const float* Wo = (const float*)d_in[9];
    const float* bo = (const float*)d_in[10];
    float* out = (float*)d_out;

    int8_t *xq0,*xq1,*xk0,*xk1,*xv0,*xv1;
    int8_t *wq0,*wq1,*wk0,*wk1,*wv0,*wv1,*wo0,*wo1;
    int8_t *qp0,*qp1,*kp0,*kp1,*vT0,*vT1,*at0,*at1,*av0,*av1;
    float *qpf,*kpf,*vTf,*avf,*sc;
    float *sxq,*sxk,*sxv,*swq,*swk,*swv,*swo,*sqp,*skp,*svT,*sat,*sav;
    cudaGetSymbolAddress((void**)&xq0, g_xq0); cudaGetSymbolAddress((void**)&xq1, g_xq1);
    cudaGetSymbolAddress((void**)&xk0, g_xk0); cudaGetSymbolAddress((void**)&xk1, g_xk1);
    cudaGetSymbolAddress((void**)&xv0, g_xv0); cudaGetSymbolAddress((void**)&xv1, g_xv1);
    cudaGetSymbolAddress((void**)&wq0, g_wq0); cudaGetSymbolAddress((void**)&wq1, g_wq1);
    cudaGetSymbolAddress((void**)&wk0, g_wk0); cudaGetSymbolAddress((void**)&wk1, g_wk1);
    cudaGetSymbolAddress((void**)&wv0, g_wv0); cudaGetSymbolAddress((void**)&wv1, g_wv1);
    cudaGetSymbolAddress((void**)&wo0, g_wo0); cudaGetSymbolAddress((void**)&wo1, g_wo1);
    cudaGetSymbolAddress((void**)&qp0, g_qp0); cudaGetSymbolAddress((void**)&qp1, g_qp1);
    cudaGetSymbolAddress((void**)&kp0, g_kp0); cudaGetSymbolAddress((void**)&kp1, g_kp1);
    cudaGetSymbolAddress((void**)&vT0, g_vT0); cudaGetSymbolAddress((void**)&vT1, g_vT1);
    cudaGetSymbolAddress((void**)&at0, g_at0); cudaGetSymbolAddress((void**)&at1, g_at1);
    cudaGetSymbolAddress((void**)&av0, g_av0); cudaGetSymbolAddress((void**)&av1, g_av1);
    cudaGetSymbolAddress((void**)&qpf, g_qpf); cudaGetSymbolAddress((void**)&kpf, g_kpf);
    cudaGetSymbolAddress((void**)&vTf, g_vTf); cudaGetSymbolAddress((void**)&avf, g_avf);
    cudaGetSymbolAddress((void**)&sc,  g_sc);
    cudaGetSymbolAddress((void**)&sxq, g_sxq); cudaGetSymbolAddress((void**)&sxk, g_sxk);
    cudaGetSymbolAddress((void**)&sxv, g_sxv);
    cudaGetSymbolAddress((void**)&swq, g_swq); cudaGetSymbolAddress((void**)&swk, g_swk);
    cudaGetSymbolAddress((void**)&swv, g_swv); cudaGetSymbolAddress((void**)&swo, g_swo);
    cudaGetSymbolAddress((void**)&sqp, g_sqp); cudaGetSymbolAddress((void**)&skp, g_skp);
    cudaGetSymbolAddress((void**)&svT, g_svT);
    cudaGetSymbolAddress((void**)&sat, g_sat); cudaGetSymbolAddress((void**)&sav, g_sav);

    cudaFuncSetAttribute(gemm_i8, cudaFuncAttributeMaxDynamicSharedMemorySize, SMEM_BYTES);

    const int D = DMOD, S = SEQ, B = BATCH;
    dim3 blk(256);
    const long SD = (long)S * D, SS = (long)S * S, DS = (long)D * S;

    // 1-5 (ncu -s 5 -c 1 captures launch 6 = q-proj)
    quant_rows<<<8192, 256>>>(q,  xq0, xq1, sxq, D);     // 1
    quant_rows<<<8192, 256>>>(k,  xk0, xk1, sxk, D);     // 2
    quant_rows<<<8192, 256>>>(v,  xv0, xv1, sxv, D);     // 3
    quant_rows<<<1024, 256>>>(Wq, wq0, wq1, swq, D);     // 4
    quant_rows<<<1024, 256>>>(Wk, wk0, wk1, swk, D);     // 5

    // 6: q-proj -> qpf                                   <-- ncu
    gemm_i8<<<dim3(8, 64), blk, SMEM_BYTES>>>(xq0, xq1, sxq, wq0, wq1, swq,
                                              bq, qpf, D, D, D, 1.0f,
                                              0, 0, 0, 0, 0, 0);
    // 7: k-proj -> kpf
    gemm_i8<<<dim3(8, 64), blk, SMEM_BYTES>>>(xk0, xk1, sxk, wk0, wk1, swk,
                                              bk, kpf, D, D, D, 1.0f,
                                              0, 0, 0, 0, 0, 0);
    // 8-9: remaining weight quants
    quant_rows<<<1024, 256>>>(Wv, wv0, wv1, swv, D);
    quant_rows<<<1024, 256>>>(Wo, wo0, wo1, swo, D);
    // 10: v-proj -> vTf (transposed [B][D][S])
    gemm_i8<<<dim3(8, 64), blk, SMEM_BYTES>>>(xv0, xv1, sxv, wv0, wv1, swv,
                                              bv, vTf, D, D, D, 1.0f,
                                              0, 0, 0, 0, 0, 1);
    // 11-13: quantize projections
    quant_rows<<<8192, 256>>>(qpf, qp0, qp1, sqp, D);
    quant_rows<<<8192, 256>>>(kpf, kp0, kp1, skp, D);
    quant_rows<<<4096, 256>>>(vTf, vT0, vT1, svT, S);
    // 14: scores = qp @ kp^T * 0.125 -> fp32
    gemm_i8<<<dim3(16, 16, B), blk, SMEM_BYTES>>>(qp0, qp1, sqp, kp0, kp1, skp,
                                                  nullptr, sc, S, D, S, 0.125f,
                                                  SD, SD, SS, S, S, 0);
    // 15: softmax -> int8 digits directly
    softmax_quant<<<(unsigned)(B * S), 256>>>(sc, at0, at1, sat, S);
    // 16: av = probs @ vT^T -> fp32
    gemm_i8<<<dim3(8, 16, B), blk, SMEM_BYTES>>>(at0, at1, sat, vT0, vT1, svT,
                                                 nullptr, avf, D, S, D, 1.0f,
                                                 SS, DS, SD, S, D, 0);
    // 17: quantize av
    quant_rows<<<8192, 256>>>(avf, av0, av1, sav, D);
    // 18: out = av @ Wo^T + bo -> fp32
    gemm_i8<<<dim3(8, 64), blk, SMEM_BYTES>>>(av0, av1, sav, wo0, wo1, swo,
                                              bo, out, D, D, D, 1.0f,
                                              0, 0, 0, 0, 0, 0);
}

// round 10
// speedup vs baseline: 3.0947x; 3.0947x over previous
#include <cuda_runtime.h>
#include <cuda_fp16.h>
#include <stdint.h>

typedef __half f16;

#define BATCH 4
#define SEQ   2048
#define DMOD  1024

#define NQ ((long)BATCH*SEQ*DMOD)   // 8,388,608
#define NW ((long)DMOD*DMOD)        // 1,048,576
#define NS ((long)BATCH*SEQ*SEQ)    // 16,777,216

// ----------------------------------------------------------------------------
// Scratch (device globals; allocation is forbidden)
// ----------------------------------------------------------------------------
__device__ __align__(256) f16 g_xq[NQ], g_xk[NQ], g_xv[NQ];        // inputs, single fp16
__device__ __align__(256) f16 g_wq_hi[NW], g_wq_lo[NW];
__device__ __align__(256) f16 g_wk_hi[NW], g_wk_lo[NW];
__device__ __align__(256) f16 g_wv_hi[NW], g_wv_lo[NW];
__device__ __align__(256) f16 g_wo_hi[NW], g_wo_lo[NW];
__device__ __align__(256) f16 g_qp[NQ];                            // q-proj, single
__device__ __align__(256) f16 g_kp_hi[NQ], g_kp_lo[NQ];            // k-proj, pair
__device__ __align__(256) f16 g_vT_hi[NQ], g_vT_lo[NQ];            // v-proj transposed [B][D][S], pair
__device__ __align__(256) float g_sc[NS];                          // scores fp32
__device__ __align__(256) f16 g_at[NS];                            // probs, single
__device__ __align__(256) f16 g_av[NQ];                            // attn@V, single

// ----------------------------------------------------------------------------
// helpers
// ----------------------------------------------------------------------------
__device__ __forceinline__ uint32_t smem_u32(const void* p) {
    uint32_t a;
    asm("{ .reg .u64 t; cvta.to.shared.u64 t, %1; cvt.u32.u64 %0, t; }" : "=r"(a) : "l"(p));
    return a;
}
__device__ __forceinline__ void cp16(uint32_t s, const void* g) {
    asm volatile("cp.async.cg.shared.global [%0], [%1], 16;" :: "r"(s), "l"(g));
}
#define CP_COMMIT() asm volatile("cp.async.commit_group;" ::: "memory")
#define CP_WAIT(n)  asm volatile("cp.async.wait_group %0;" :: "n"(n) : "memory")

__device__ __forceinline__ void ldsm4(uint32_t& r0, uint32_t& r1, uint32_t& r2,
                                      uint32_t& r3, uint32_t addr) {
    asm volatile("ldmatrix.sync.aligned.m8n8.x4.shared.b16 {%0,%1,%2,%3}, [%4];"
                 : "=r"(r0), "=r"(r1), "=r"(r2), "=r"(r3) : "r"(addr));
}
__device__ __forceinline__ void mma16816(float* d, const uint32_t* a, const uint32_t* b) {
    asm volatile(
        "mma.sync.aligned.m16n8k16.row.col.f32.f16.f16.f32 "
        "{%0,%1,%2,%3}, {%4,%5,%6,%7}, {%8,%9}, {%0,%1,%2,%3};"
        : "+f"(d[0]), "+f"(d[1]), "+f"(d[2]), "+f"(d[3])
        : "r"(a[0]), "r"(a[1]), "r"(a[2]), "r"(a[3]), "r"(b[0]), "r"(b[1]));
}

// ----------------------------------------------------------------------------
// fused conversions
// ----------------------------------------------------------------------------
__global__ void conv_x3(const float* __restrict__ q, const float* __restrict__ k,
                        const float* __restrict__ v) {
    long i = (long)blockIdx.x * blockDim.x + threadIdx.x;
    if (i >= 3 * NQ) return;
    const float* src; f16* dst; long j;
    if (i < NQ)          { src = q; dst = g_xq; j = i; }
    else if (i < 2 * NQ) { src = k; dst = g_xk; j = i - NQ; }
    else                 { src = v; dst = g_xv; j = i - 2 * NQ; }
    dst[j] = __float2half_rn(src[j]);
}

__global__ void split_w4(const float* __restrict__ wq, const float* __restrict__ wk,
                         const float* __restrict__ wv, const float* __restrict__ wo) {
    long i = (long)blockIdx.x * blockDim.x + threadIdx.x;
    if (i >= 4 * NW) return;
    const float* src; f16 *hi, *lo; long j;
    if (i < NW)          { src = wq; hi = g_wq_hi; lo = g_wq_lo; j = i; }
    else if (i < 2 * NW) { src = wk; hi = g_wk_hi; lo = g_wk_lo; j = i - NW; }
    else if (i < 3 * NW) { src = wv; hi = g_wv_hi; lo = g_wv_lo; j = i - 2 * NW; }
    else                 { src = wo; hi = g_wo_hi; lo = g_wo_lo; j = i - 3 * NW; }
    float val = src[j];
    f16 h = __float2half_rn(val);
    hi[j] = h;
    lo[j] = __float2half_rn(val - __half2float(h));
}

// ----------------------------------------------------------------------------
// Row softmax fp32 -> fp16   (n == 2048, 256 threads)
// ----------------------------------------------------------------------------
__global__ void softmax_f16(const float* __restrict__ S, f16* __restrict__ P, int n) {
    const float* row = S + (long)blockIdx.x * n;
    __shared__ float red[256];
    const int t = threadIdx.x;
    float e[8];
    float m = -1e30f;
#pragma unroll
    for (int i = 0; i < 8; i++) { e[i] = row[t + i * 256]; m = fmaxf(m, e[i]); }
    red[t] = m; __syncthreads();
    for (int s = 128; s > 0; s >>= 1) {
        if (t < s) red[t] = fmaxf(red[t], red[t + s]);
        __syncthreads();
    }
    m = red[0]; __syncthreads();
    float sum = 0.f;
#pragma unroll
    for (int i = 0; i < 8; i++) { e[i] = __expf(e[i] - m); sum += e[i]; }
    red[t] = sum; __syncthreads();
    for (int s = 128; s > 0; s >>= 1) {
        if (t < s) red[t] += red[t + s];
        __syncthreads();
    }
    float inv = 1.0f / red[0];
#pragma unroll
    for (int i = 0; i < 8; i++)
        P[(long)blockIdx.x * n + t + i * 256] = __float2half_rn(e[i] * inv);
}

// ----------------------------------------------------------------------------
// mma.sync fp16 2-product GEMM (NT):  C[m,n] = alpha * sum_k A[m,k]*B[n,k] (+bias)
//   A single fp16, B = Bh + Bl fp16 pair.
//   CTA tile 64x64, BK=32, 2-stage cp.async, 4 warps (32x32 each), 128 threads.
//   High-occupancy variant: launch_bounds(128, 6) -> target 24 warps/SM.
//   mode 0: fp32 out.  mode 1: fp16 single out.  mode 2: fp16 pair out.
// ----------------------------------------------------------------------------
#define BM 64
#define BN 64
#define BK 32
#define ROWB 80              // smem row stride bytes (32 fp16 = 64B data + 16B pad)
#define TILEB (64 * ROWB)    // 5120 B per matrix tile
#define SM_A  0
#define SM_BH TILEB
#define SM_BL (2 * TILEB)
#define STAGEB (3 * TILEB)   // 15360 B
#define SMEM_BYTES (2 * STAGEB)   // 30720 B

__global__ void __launch_bounds__(128, 6) gemm2(
    const f16* __restrict__ A,
    const f16* __restrict__ Bhi, const f16* __restrict__ Blo,
    const float* __restrict__ bias,
    float* __restrict__ Cf, f16* __restrict__ C1, f16* __restrict__ C2,
    int N, int K, int ldc, float alpha,
    long sA, long sB, long sC, int mode, int transC)
{
    extern __shared__ char smem[];
    const uint32_t sb = smem_u32(smem);
    const int tid = threadIdx.x;
    const int wid = tid >> 5;            // 0..3
    const int lid = tid & 31;
    const int wm = (wid & 1) * 32;       // warp M offset in CTA tile
    const int wn = (wid >> 1) * 32;      // warp N offset
    const long bz = blockIdx.z;
    const int m0 = blockIdx.y * BM;
    const int n0 = blockIdx.x * BN;

    const f16* pA  = A   + bz * sA;
    const f16* pBh = Bhi + bz * sB;
    const f16* pBl = Blo + bz * sB;

    const int lrow = tid >> 1;           // 0..63 row for loads
    const int lch  = (tid & 1) * 32;     // 0 or 32 byte offset

    float acc[2][4][4];
#pragma unroll
    for (int i = 0; i < 2; ++i)
#pragma unroll
        for (int j = 0; j < 4; ++j)
#pragma unroll
            for (int c = 0; c < 4; ++c) acc[i][j][c] = 0.f;

    const int nch = K / BK;

    // ---- stage loader: 6 x cp.async per thread (1 row x 3 tiles x 32B) ----
    auto issue = [&](int ch, int buf) {
        const int k0 = ch * BK;
        const uint32_t s0 = sb + buf * STAGEB;
        const uint32_t so = (uint32_t)(lrow * ROWB + lch);
        const long goA = (long)(m0 + lrow) * K + k0 + (lch >> 1);
        const long goB = (long)(n0 + lrow) * K + k0 + (lch >> 1);
        cp16(s0 + SM_A  + so,      pA  + goA);
        cp16(s0 + SM_A  + so + 16, pA  + goA + 8);
        cp16(s0 + SM_BH + so,      pBh + goB);
        cp16(s0 + SM_BH + so + 16, pBh + goB + 8);
        cp16(s0 + SM_BL + so,      pBl + goB);
        cp16(s0 + SM_BL + so + 16, pBl + goB + 8);
    };

    issue(0, 0);
    CP_COMMIT();

    // ldmatrix lane addressing (within a stage buffer)
    const int a_row = lid & 15;                    // 0..15
    const int a_col = (lid >> 4) * 16;             // 0 or 16 bytes
    const int b_nin = ((lid >> 4) & 1) * 8 + (lid & 7);  // n within 16-block
    const int b_col = ((lid >> 3) & 1) * 16;       // k-half bytes

    for (int ch = 0; ch < nch; ++ch) {
        if (ch + 1 < nch) { issue(ch + 1, (ch + 1) & 1); CP_COMMIT(); CP_WAIT(1); }
        else              { CP_WAIT(0); }
        __syncthreads();

        const uint32_t s0 = sb + (ch & 1) * STAGEB;

#pragma unroll
        for (int ks = 0; ks < 2; ++ks) {
            const int kb = ks * 32 + a_col;        // A k-byte offset for this lane
            uint32_t af[2][4];
#pragma unroll
            for (int mt = 0; mt < 2; ++mt) {
                const uint32_t ro = (uint32_t)((wm + mt * 16 + a_row) * ROWB);
                ldsm4(af[mt][0], af[mt][1], af[mt][2], af[mt][3], s0 + SM_A + ro + kb);
            }
            uint32_t bh[2][4], bl[2][4];
#pragma unroll
            for (int np = 0; np < 2; ++np) {
                const uint32_t ro = (uint32_t)((wn + np * 16 + b_nin) * ROWB + ks * 32 + b_col);
                ldsm4(bh[np][0], bh[np][1], bh[np][2], bh[np][3], s0 + SM_BH + ro);
                ldsm4(bl[np][0], bl[np][1], bl[np][2], bl[np][3], s0 + SM_BL + ro);
            }
#pragma unroll
            for (int mt = 0; mt < 2; ++mt) {
#pragma unroll
                for (int nt = 0; nt < 4; ++nt) {
                    const int np = nt >> 1, sel = (nt & 1) * 2;
                    mma16816(acc[mt][nt], af[mt], &bh[np][sel]);
                    mma16816(acc[mt][nt], af[mt], &bl[np][sel]);
                }
            }
        }
        __syncthreads();
    }

    // ---- epilogue ----
    const int gr = lid >> 2;             // group row 0..7
    const int tg = lid & 3;              // col pair 0..3
#pragma unroll
    for (int mt = 0; mt < 2; ++mt) {
#pragma unroll
        for (int nt = 0; nt < 4; ++nt) {
#pragma unroll
            for (int h = 0; h < 2; ++h) {        // c0c1 vs c2c3 (row +8)
                const int m = m0 + wm + mt * 16 + gr + h * 8;
#pragma unroll
                for (int c = 0; c < 2; ++c) {
                    const int n = n0 + wn + nt * 8 + tg * 2 + c;
                    float v = acc[mt][nt][h * 2 + c] * alpha;
                    if (bias) v += __ldg(bias + n);
                    if (mode == 0) {
                        Cf[bz * sC + (long)m * ldc + n] = v;
                    } else {
                        long o = transC ? (bz * sC + (long)n * ldc + m)
                                        : (bz * sC + (long)m * ldc + n);
                        f16 hh = __float2half_rn(v);
                        C1[o] = hh;
                        if (mode == 2)
                            C2[o] = __float2half_rn(v - __half2float(hh));
                    }
                }
            }
        }
    }
}

// ----------------------------------------------------------------------------
// launch
// ----------------------------------------------------------------------------
extern "C" void kernel_launch(void* const* d_in, const int* in_sizes, int n_in,
                              void* d_out, int out_size) {
    const float* q  = (const float*)d_in[0];
    const float* k  = (const float*)d_in[1];
    const float* v  = (const float*)d_in[2];
    const float* Wq = (const float*)d_in[3];
    const float* bq = (const float*)d_in[4];
    const float* Wk = (const float*)d_in[5];
    const float* bk = (const float*)d_in[6];
    const float* Wv = (const float*)d_in[7];
    const float* bv = (const float*)d_in[8];
    const float* Wo = (const float*)d_in[9];
    const float* bo = (const float*)d_in[10];
    float* out = (float*)d_out;

    f16 *xq, *xk, *xv, *qp, *at, *av;
    f16 *wqh, *wql, *wkh, *wkl, *wvh, *wvl, *woh, *wol;
    f16 *kph, *kpl, *vTh, *vTl;
    float* sc;
    cudaGetSymbolAddress((void**)&xq, g_xq);
    cudaGetSymbolAddress((void**)&xk, g_xk);
    cudaGetSymbolAddress((void**)&xv, g_xv);
    cudaGetSymbolAddress((void**)&wqh, g_wq_hi); cudaGetSymbolAddress((void**)&wql, g_wq_lo);
    cudaGetSymbolAddress((void**)&wkh, g_wk_hi); cudaGetSymbolAddress((void**)&wkl, g_wk_lo);
    cudaGetSymbolAddress((void**)&wvh, g_wv_hi); cudaGetSymbolAddress((void**)&wvl, g_wv_lo);
    cudaGetSymbolAddress((void**)&woh, g_wo_hi); cudaGetSymbolAddress((void**)&wol, g_wo_lo);
    cudaGetSymbolAddress((void**)&qp, g_qp);
    cudaGetSymbolAddress((void**)&kph, g_kp_hi); cudaGetSymbolAddress((void**)&kpl, g_kp_lo);
    cudaGetSymbolAddress((void**)&vTh, g_vT_hi); cudaGetSymbolAddress((void**)&vTl, g_vT_lo);
    cudaGetSymbolAddress((void**)&at, g_at);
    cudaGetSymbolAddress((void**)&av, g_av);
    cudaGetSymbolAddress((void**)&sc, g_sc);

    cudaFuncSetAttribute(gemm2, cudaFuncAttributeMaxDynamicSharedMemorySize, SMEM_BYTES);

    const int D = DMOD, S = SEQ, B = BATCH;
    dim3 blk(128);
    dim3 gp(D / BN, (B * S) / BM, 1);    // (16, 128)
    dim3 gv(D / BN, S / BM, B);          // (16, 32, 4)
    dim3 gs(S / BN, S / BM, B);          // (32, 32, 4)
    dim3 ga(D / BN, S / BM, B);          // (16, 32, 4)

    // 1-2: fused conversions
    conv_x3 <<<(unsigned)((3 * NQ + 511) / 512), 512>>>(q, k, v);
    split_w4<<<(unsigned)((4 * NW + 511) / 512), 512>>>(Wq, Wk, Wv, Wo);

    // 3: q projection -> qp (fp16 single)
    gemm2<<<gp, blk, SMEM_BYTES>>>(xq, wqh, wql, bq, nullptr, qp, nullptr,
                                   D, D, D, 1.0f, 0, 0, 0, 1, 0);
    // 4: k projection -> kp (fp16 pair)
    gemm2<<<gp, blk, SMEM_BYTES>>>(xk, wkh, wkl, bk, nullptr, kph, kpl,
                                   D, D, D, 1.0f, 0, 0, 0, 2, 0);
    // 5: v projection -> vT (fp16 pair, transposed [B][D][S])
    gemm2<<<gv, blk, SMEM_BYTES>>>(xv, wvh, wvl, bv, nullptr, vTh, vTl,
                                   D, D, /*ldc=*/S, 1.0f,
                                   (long)S * D, 0, (long)D * S, 2, 1);
    // 6: scores = qp @ kp^T * 0.125 -> fp32           <-- ncu -s 5 -c 1 capture
    gemm2<<<gs, blk, SMEM_BYTES>>>(qp, kph, kpl, nullptr, sc, nullptr, nullptr,
                                   S, D, S, 0.125f,
                                   (long)S * D, (long)S * D, (long)S * S, 0, 0);
    // 7: softmax -> fp16 probs
    softmax_f16<<<(unsigned)(B * S), 256>>>(sc, at, S);
    // 8: att = probs @ vT^T -> fp16 single
    gemm2<<<ga, blk, SMEM_BYTES>>>(at, vTh, vTl, nullptr, nullptr, av, nullptr,
                                   D, S, D, 1.0f,
                                   (long)S * S, (long)D * S, (long)S * D, 1, 0);
    // 9: out = att @ Wo^T + bo -> fp32
    gemm2<<<gp, blk, SMEM_BYTES>>>(av, woh, wol, bo, out, nullptr, nullptr,
                                   D, D, D, 1.0f, 0, 0, 0, 0, 0);
}